// round 5
// baseline (speedup 1.0000x reference)
#include <cuda_runtime.h>

static constexpr int B = 16, C = 21, H = 512, W = 512;
static constexpr int HW = H * W;            // 262144
static constexpr int NPLANES = B * C;       // 336
static constexpr int P4 = HW / 4;           // 65536 float4 per plane
static constexpr int TPB = 256;
static constexpr int BLOCKS_PER_PLANE = 64;
static constexpr int ITERS = P4 / (TPB * BLOCKS_PER_PLANE); // 4

// Per-block partial sums: every slot is written on every call -> no zeroing
// pass needed, no atomics, fully deterministic under graph replay.
__device__ __align__(16) float g_pta[NPLANES * BLOCKS_PER_PLANE];
__device__ __align__(16) float g_ptb[NPLANES * BLOCKS_PER_PLANE];
__device__ __align__(16) float g_pit[NPLANES * BLOCKS_PER_PLANE];

__global__ __launch_bounds__(TPB) void sums_kernel(
    const float4* __restrict__ yp, const float4* __restrict__ yt)
{
    const int plane = blockIdx.x / BLOCKS_PER_PLANE;
    const int seg   = blockIdx.x % BLOCKS_PER_PLANE;
    const size_t base = (size_t)plane * P4 + (size_t)seg * (TPB * ITERS);

    const float4* p = yp + base;
    const float4* t = yt + base;

    float ta = 0.0f, tb = 0.0f, it = 0.0f;
    #pragma unroll
    for (int k = 0; k < ITERS; k++) {
        float4 a = p[threadIdx.x + k * TPB];   // y_pred
        float4 b = t[threadIdx.x + k * TPB];   // y_true
        tb += (a.x + a.y) + (a.z + a.w);
        ta += (b.x + b.y) + (b.z + b.w);
        it += a.x * b.x + a.y * b.y + a.z * b.z + a.w * b.w;
    }

    // warp reduce
    #pragma unroll
    for (int o = 16; o > 0; o >>= 1) {
        ta += __shfl_down_sync(0xFFFFFFFFu, ta, o);
        tb += __shfl_down_sync(0xFFFFFFFFu, tb, o);
        it += __shfl_down_sync(0xFFFFFFFFu, it, o);
    }

    __shared__ float sta[TPB / 32], stb[TPB / 32], sit[TPB / 32];
    int w = threadIdx.x >> 5, l = threadIdx.x & 31;
    if (l == 0) { sta[w] = ta; stb[w] = tb; sit[w] = it; }
    __syncthreads();

    if (threadIdx.x == 0) {
        float A = 0.0f, Bv = 0.0f, I = 0.0f;
        #pragma unroll
        for (int i = 0; i < TPB / 32; i++) { A += sta[i]; Bv += stb[i]; I += sit[i]; }
        const int slot = plane * BLOCKS_PER_PLANE + seg;
        g_pta[slot] = A;
        g_ptb[slot] = Bv;
        g_pit[slot] = I;
    }
}

__global__ __launch_bounds__(512) void finalize_kernel(
    const int* __restrict__ bg_ptr, float* __restrict__ out)
{
    __shared__ float s_dice[NPLANES];
    __shared__ float s_valid[NPLANES];

    const int tid = threadIdx.x;

    // Stage 1: one thread per plane reduces its 64 partials (16 float4 x 3).
    if (tid < NPLANES) {
        const float4* pa = (const float4*)&g_pta[tid * BLOCKS_PER_PLANE];
        const float4* pb = (const float4*)&g_ptb[tid * BLOCKS_PER_PLANE];
        const float4* pi = (const float4*)&g_pit[tid * BLOCKS_PER_PLANE];
        float ta = 0.0f, tb = 0.0f, it = 0.0f;
        #pragma unroll
        for (int i = 0; i < BLOCKS_PER_PLANE / 4; i++) {
            float4 a = pa[i], b = pb[i], c = pi[i];
            ta += (a.x + a.y) + (a.z + a.w);
            tb += (b.x + b.y) + (b.z + b.w);
            it += (c.x + c.y) + (c.z + c.w);
        }
        float valid = (ta != 0.0f) ? 1.0f : 0.0f;
        s_dice[tid]  = valid * (2.0f * it / (ta + tb + 1e-11f));
        s_valid[tid] = valid;
    }
    __syncthreads();

    // Stage 2: one lane per batch, replicating the reference epilogue.
    if (tid < 32) {
        const int bg = *bg_ptr;
        const int b = tid;
        float tmp = 0.0f, bv = 0.0f;
        if (b < B) {
            float cnt = 0.0f, sd = 0.0f;
            for (int c = bg; c < C; c++) {
                cnt += s_valid[b * C + c];
                sd  += s_dice[b * C + c];
            }
            float denom = cnt - (float)bg;      // cpt2 - bg, as in reference
            if (denom != 0.0f) {
                tmp = sd / denom;
                bv = 1.0f;
            }
        }
        #pragma unroll
        for (int o = 16; o > 0; o >>= 1) {
            tmp += __shfl_down_sync(0xFFFFFFFFu, tmp, o);
            bv  += __shfl_down_sync(0xFFFFFFFFu, bv,  o);
        }
        if (tid == 0) {
            float cpt1 = bv;
            float loss = 1.0f - tmp / fmaxf(cpt1, 1.0f);
            out[0] = (cpt1 > 0.0f) ? loss : -1.0f;
        }
    }
}

extern "C" void kernel_launch(void* const* d_in, const int* in_sizes, int n_in,
                              void* d_out, int out_size)
{
    const float4* y_pred = (const float4*)d_in[0];
    const float4* y_true = (const float4*)d_in[1];
    const int*    bg     = (const int*)d_in[2];
    float*        out    = (float*)d_out;

    sums_kernel<<<NPLANES * BLOCKS_PER_PLANE, TPB>>>(y_pred, y_true);
    finalize_kernel<<<1, 512>>>(bg, out);
}

// round 6
// speedup vs baseline: 1.0362x; 1.0362x over previous
#include <cuda_runtime.h>

static constexpr int B = 16, C = 21, H = 512, W = 512;
static constexpr int HW = H * W;            // 262144
static constexpr int NPLANES = B * C;       // 336
static constexpr int P4 = HW / 4;           // 65536 float4 per plane
static constexpr int TPB = 256;
static constexpr int BPP = 64;              // blocks per plane
static constexpr int ITERS = P4 / (TPB * BPP); // 4

// Per-block partials (every slot written every call -> no init needed).
__device__ float g_pta[NPLANES * BPP];
__device__ float g_ptb[NPLANES * BPP];
__device__ float g_pit[NPLANES * BPP];
// Per-plane results.
__device__ float g_dice[NPLANES];
__device__ float g_valid[NPLANES];
// Counters: zero-initialized at module load; each use resets them to 0 before
// the kernel ends, so graph replays are deterministic.
__device__ int g_cnt[NPLANES];
__device__ int g_done;

__global__ __launch_bounds__(TPB) void dice_kernel(
    const float4* __restrict__ yp, const float4* __restrict__ yt,
    const int* __restrict__ bg_ptr, float* __restrict__ out)
{
    const int plane = blockIdx.x / BPP;
    const int seg   = blockIdx.x % BPP;
    const size_t base = (size_t)plane * P4 + (size_t)seg * (TPB * ITERS);

    const float4* p = yp + base;
    const float4* t = yt + base;

    // ---- streaming phase (DRAM-bound) ----
    float ta = 0.0f, tb = 0.0f, it = 0.0f;
    #pragma unroll
    for (int k = 0; k < ITERS; k++) {
        float4 a = __ldcs(&p[threadIdx.x + k * TPB]);   // y_pred
        float4 b = __ldcs(&t[threadIdx.x + k * TPB]);   // y_true
        tb += (a.x + a.y) + (a.z + a.w);
        ta += (b.x + b.y) + (b.z + b.w);
        it += a.x * b.x + a.y * b.y + a.z * b.z + a.w * b.w;
    }

    // ---- block reduce ----
    #pragma unroll
    for (int o = 16; o > 0; o >>= 1) {
        ta += __shfl_down_sync(0xFFFFFFFFu, ta, o);
        tb += __shfl_down_sync(0xFFFFFFFFu, tb, o);
        it += __shfl_down_sync(0xFFFFFFFFu, it, o);
    }

    __shared__ float sta[TPB / 32], stb[TPB / 32], sit[TPB / 32];
    __shared__ int s_last;
    const int wid = threadIdx.x >> 5, lid = threadIdx.x & 31;
    if (lid == 0) { sta[wid] = ta; stb[wid] = tb; sit[wid] = it; }
    __syncthreads();

    if (threadIdx.x == 0) {
        float A = 0.0f, Bv = 0.0f, I = 0.0f;
        #pragma unroll
        for (int i = 0; i < TPB / 32; i++) { A += sta[i]; Bv += stb[i]; I += sit[i]; }
        const int slot = plane * BPP + seg;
        __stcg(&g_pta[slot], A);
        __stcg(&g_ptb[slot], Bv);
        __stcg(&g_pit[slot], I);
        __threadfence();
        int old = atomicAdd(&g_cnt[plane], 1);
        s_last = (old == BPP - 1);
    }
    __syncthreads();
    if (!s_last || threadIdx.x >= 32) return;

    // ---- this block is the last of its plane: reduce 64 partials (warp 0) ----
    {
        const int b0 = plane * BPP + lid;
        float A = __ldcg(&g_pta[b0]) + __ldcg(&g_pta[b0 + 32]);
        float Bv = __ldcg(&g_ptb[b0]) + __ldcg(&g_ptb[b0 + 32]);
        float I = __ldcg(&g_pit[b0]) + __ldcg(&g_pit[b0 + 32]);
        #pragma unroll
        for (int o = 16; o > 0; o >>= 1) {
            A  += __shfl_down_sync(0xFFFFFFFFu, A,  o);
            Bv += __shfl_down_sync(0xFFFFFFFFu, Bv, o);
            I  += __shfl_down_sync(0xFFFFFFFFu, I,  o);
        }
        int fin = 0;
        if (lid == 0) {
            float valid = (A != 0.0f) ? 1.0f : 0.0f;
            __stcg(&g_dice[plane], valid * (2.0f * I / (A + Bv + 1e-11f)));
            __stcg(&g_valid[plane], valid);
            g_cnt[plane] = 0;               // reset for next graph replay
            __threadfence();
            int old2 = atomicAdd(&g_done, 1);
            fin = (old2 == NPLANES - 1);
        }
        fin = __shfl_sync(0xFFFFFFFFu, fin, 0);
        if (!fin) return;
    }

    // ---- very last plane finisher: batch epilogue (warp 0, lanes 0..B-1) ----
    {
        __threadfence();
        const int bg = *bg_ptr;
        const int b = lid;
        float tmp = 0.0f, bv = 0.0f;
        if (b < B) {
            float cnt = 0.0f, sd = 0.0f;
            for (int c = bg; c < C; c++) {
                cnt += __ldcg(&g_valid[b * C + c]);
                sd  += __ldcg(&g_dice[b * C + c]);
            }
            float denom = cnt - (float)bg;      // cpt2 - bg, as in reference
            if (denom != 0.0f) {
                tmp = sd / denom;
                bv = 1.0f;
            }
        }
        #pragma unroll
        for (int o = 16; o > 0; o >>= 1) {
            tmp += __shfl_down_sync(0xFFFFFFFFu, tmp, o);
            bv  += __shfl_down_sync(0xFFFFFFFFu, bv,  o);
        }
        if (lid == 0) {
            float cpt1 = bv;
            float loss = 1.0f - tmp / fmaxf(cpt1, 1.0f);
            out[0] = (cpt1 > 0.0f) ? loss : -1.0f;
            g_done = 0;                     // reset for next graph replay
        }
    }
}

extern "C" void kernel_launch(void* const* d_in, const int* in_sizes, int n_in,
                              void* d_out, int out_size)
{
    const float4* y_pred = (const float4*)d_in[0];
    const float4* y_true = (const float4*)d_in[1];
    const int*    bg     = (const int*)d_in[2];
    float*        out    = (float*)d_out;

    dice_kernel<<<NPLANES * BPP, TPB>>>(y_pred, y_true, bg, out);
}